// round 15
// baseline (speedup 1.0000x reference)
#include <cuda_runtime.h>
#include <cuda_bf16.h>
#include <mma.h>
#include <cstdint>

using namespace nvcuda;

// Problem constants
static constexpr int Bc = 4, Tc = 2048, Cc = 1024, Hc = 16, Dc = 64;
static constexpr int Mrows = Bc * Tc;            // 8192
static constexpr int ELEMS = Mrows * Cc;         // 8388608
static constexpr int WELEMS = Cc * Cc;           // 1048576

// Scratch (device globals — no allocation allowed). All hi/lo bf16 pairs.
__device__ __nv_bfloat16 g_xhi[ELEMS], g_xlo[ELEMS];
__device__ __nv_bfloat16 g_qhi[ELEMS], g_qlo[ELEMS];
__device__ __nv_bfloat16 g_khi[ELEMS], g_klo[ELEMS];
__device__ __nv_bfloat16 g_vhi[ELEMS], g_vlo[ELEMS];
__device__ __nv_bfloat16 g_yhi[ELEMS], g_ylo[ELEMS];
__device__ __nv_bfloat16 g_whi[4][WELEMS], g_wlo[4][WELEMS];

// ---------------------------------------------------------------------------
// PTX primitives (plain-sm_103 legal)
// ---------------------------------------------------------------------------
__device__ __forceinline__ uint32_t smem_u32(const void* p) {
    uint32_t a;
    asm("{ .reg .u64 t; cvta.to.shared.u64 t, %1; cvt.u32.u64 %0, t; }" : "=r"(a) : "l"(p));
    return a;
}
__device__ __forceinline__ void cp16(uint32_t dst, const void* src) {
    asm volatile("cp.async.cg.shared.global [%0], [%1], 16;" :: "r"(dst), "l"(src));
}
__device__ __forceinline__ void cp_commit() { asm volatile("cp.async.commit_group;" ::: "memory"); }
template<int N> __device__ __forceinline__ void cp_wait() {
    asm volatile("cp.async.wait_group %0;" :: "n"(N) : "memory");
}
__device__ __forceinline__ void ldsm4(uint32_t& r0, uint32_t& r1, uint32_t& r2, uint32_t& r3, uint32_t a) {
    asm volatile("ldmatrix.sync.aligned.m8n8.x4.shared.b16 {%0,%1,%2,%3}, [%4];"
                 : "=r"(r0), "=r"(r1), "=r"(r2), "=r"(r3) : "r"(a));
}
__device__ __forceinline__ void ldsm2(uint32_t& r0, uint32_t& r1, uint32_t a) {
    asm volatile("ldmatrix.sync.aligned.m8n8.x2.shared.b16 {%0,%1}, [%2];"
                 : "=r"(r0), "=r"(r1) : "r"(a));
}
__device__ __forceinline__ void ldsm2t(uint32_t& r0, uint32_t& r1, uint32_t a) {
    asm volatile("ldmatrix.sync.aligned.m8n8.x2.trans.shared.b16 {%0,%1}, [%2];"
                 : "=r"(r0), "=r"(r1) : "r"(a));
}
__device__ __forceinline__ void mma16816(float* c, uint32_t a0, uint32_t a1, uint32_t a2, uint32_t a3,
                                         uint32_t b0, uint32_t b1) {
    asm volatile("mma.sync.aligned.m16n8k16.row.col.f32.bf16.bf16.f32 "
                 "{%0,%1,%2,%3}, {%4,%5,%6,%7}, {%8,%9}, {%0,%1,%2,%3};"
                 : "+f"(c[0]), "+f"(c[1]), "+f"(c[2]), "+f"(c[3])
                 : "r"(a0), "r"(a1), "r"(a2), "r"(a3), "r"(b0), "r"(b1));
}
__device__ __forceinline__ void split_pack(float x, float y, uint32_t& hi, uint32_t& lo) {
    __nv_bfloat16 hx = __float2bfloat16_rn(x), hy = __float2bfloat16_rn(y);
    float lx = x - __bfloat162float(hx), ly = y - __bfloat162float(hy);
    __nv_bfloat162 hv(hx, hy);
    __nv_bfloat162 lv(__float2bfloat16_rn(lx), __float2bfloat16_rn(ly));
    hi = *reinterpret_cast<uint32_t*>(&hv);
    lo = *reinterpret_cast<uint32_t*>(&lv);
}

// ---------------------------------------------------------------------------
// fp32 -> bf16 hi/lo split conversion (x and weights)
// ---------------------------------------------------------------------------
__global__ __launch_bounds__(256)
void split_bf16(const float* __restrict__ in,
                __nv_bfloat16* __restrict__ hi,
                __nv_bfloat16* __restrict__ lo, int n4)
{
    int i = blockIdx.x * blockDim.x + threadIdx.x;
    if (i >= n4) return;
    int idx = i * 4;
    float4 v = *(const float4*)(in + idx);
    uint32_t h0, l0, h1, l1;
    split_pack(v.x, v.y, h0, l0);
    split_pack(v.z, v.w, h1, l1);
    *(uint2*)(hi + idx) = make_uint2(h0, h1);
    *(uint2*)(lo + idx) = make_uint2(l0, l1);
}

// ---------------------------------------------------------------------------
// Fused QKV GEMM (R10, proven): block 256x128, warp 64x64, 3-stage cp.async.
// ---------------------------------------------------------------------------
#define ASTR 24
static constexpr int QBM = 256;
static constexpr int Q_SAH = 0;
static constexpr int Q_SAL = 256 * ASTR;
static constexpr int Q_SBH = 2 * 256 * ASTR;
static constexpr int Q_SBL = Q_SBH + 128 * ASTR;
static constexpr int Q_STAGE_E = Q_SBL + 128 * ASTR;
static constexpr int Q_STAGES = 3;
static constexpr int Q_TILES_BYTES = Q_STAGES * Q_STAGE_E * 2;   // 110592
static constexpr int Q_PATCH_BYTES = 8 * 16 * 20 * 4;            // 10240
static constexpr int Q_SMEM = Q_TILES_BYTES + Q_PATCH_BYTES;     // 120832

__global__ __launch_bounds__(256)
void gemm_qkv_fused(const __nv_bfloat16* __restrict__ Xhi,
                    const __nv_bfloat16* __restrict__ Xlo,
                    const __nv_bfloat16* __restrict__ Whi,
                    const __nv_bfloat16* __restrict__ Wlo,
                    const float* __restrict__ bq,
                    const float* __restrict__ bk,
                    const float* __restrict__ bv,
                    __nv_bfloat16* __restrict__ Qhi, __nv_bfloat16* __restrict__ Qlo,
                    __nv_bfloat16* __restrict__ Khi, __nv_bfloat16* __restrict__ Klo,
                    __nv_bfloat16* __restrict__ Vhi, __nv_bfloat16* __restrict__ Vlo)
{
    extern __shared__ char gsm[];
    __nv_bfloat16* tiles = (__nv_bfloat16*)gsm;
    float* patches = (float*)(gsm + Q_TILES_BYTES);
    const uint32_t tiles_u = smem_u32(tiles);

    const int tid = threadIdx.x;
    const int wid = tid >> 5;
    const int lane = tid & 31;
    const int wm = wid & 3;
    const int wn = wid >> 2;
    const int m0 = blockIdx.y * QBM;
    const int gn0 = blockIdx.x * 128;
    const int which = gn0 >> 10;
    const int n0w = gn0 & 1023;
    const int K = Cc;

    const __nv_bfloat16* Bh = Whi + (size_t)which * WELEMS;
    const __nv_bfloat16* Bl = Wlo + (size_t)which * WELEMS;

    auto prefetch = [&](int stage, int k0) {
        const uint32_t sb = tiles_u + (uint32_t)(stage * Q_STAGE_E * 2);
#pragma unroll
        for (int u = 0; u < 4; u++) {
            int idx = tid + u * 256;
            int op = idx >> 9;
            int rem = idx & 511;
            int r = rem >> 1, ch = rem & 1;
            const __nv_bfloat16* s =
                (op ? Xlo : Xhi) + (size_t)(m0 + r) * K + k0 + ch * 8;
            cp16(sb + (uint32_t)(((op ? Q_SAL : Q_SAH) + r * ASTR) * 2 + ch * 16), s);
        }
#pragma unroll
        for (int u = 0; u < 2; u++) {
            int idx = tid + u * 256;
            int op = idx >> 8;
            int rem = idx & 255;
            int r = rem >> 1, ch = rem & 1;
            const __nv_bfloat16* s =
                (op ? Bl : Bh) + (size_t)(n0w + r) * K + k0 + ch * 8;
            cp16(sb + (uint32_t)(((op ? Q_SBL : Q_SBH) + r * ASTR) * 2 + ch * 16), s);
        }
    };

    prefetch(0, 0);  cp_commit();
    prefetch(1, 16); cp_commit();

    wmma::fragment<wmma::accumulator, 16, 16, 16, float> acc[4][4];
#pragma unroll
    for (int i = 0; i < 4; i++)
#pragma unroll
        for (int j = 0; j < 4; j++)
            wmma::fill_fragment(acc[i][j], 0.0f);

    const int KT = K / 16;
    for (int kt = 0; kt < KT; kt++) {
        const int s = kt % Q_STAGES;
        if (kt == KT - 1) cp_wait<0>(); else cp_wait<1>();
        __syncthreads();

        __nv_bfloat16* st = tiles + s * Q_STAGE_E;
        wmma::fragment<wmma::matrix_a, 16, 16, 16, __nv_bfloat16, wmma::row_major> ah[4], al[4];
#pragma unroll
        for (int i = 0; i < 4; i++) {
            wmma::load_matrix_sync(ah[i], st + Q_SAH + (wm * 64 + i * 16) * ASTR, ASTR);
            wmma::load_matrix_sync(al[i], st + Q_SAL + (wm * 64 + i * 16) * ASTR, ASTR);
        }
#pragma unroll
        for (int j = 0; j < 4; j++) {
            wmma::fragment<wmma::matrix_b, 16, 16, 16, __nv_bfloat16, wmma::col_major> bh, bl;
            wmma::load_matrix_sync(bh, st + Q_SBH + (wn * 64 + j * 16) * ASTR, ASTR);
            wmma::load_matrix_sync(bl, st + Q_SBL + (wn * 64 + j * 16) * ASTR, ASTR);
#pragma unroll
            for (int i = 0; i < 4; i++) {
                wmma::mma_sync(acc[i][j], ah[i], bh, acc[i][j]);
                wmma::mma_sync(acc[i][j], al[i], bh, acc[i][j]);
                wmma::mma_sync(acc[i][j], ah[i], bl, acc[i][j]);
            }
        }
        if (kt + 2 < KT) { prefetch((kt + 2) % Q_STAGES, (kt + 2) * 16); cp_commit(); }
    }

    const float* biasv = (which == 0) ? bq : (which == 1) ? bk : bv;
    __nv_bfloat16* Ch = (which == 0) ? Qhi : (which == 1) ? Khi : Vhi;
    __nv_bfloat16* Cl = (which == 0) ? Qlo : (which == 1) ? Klo : Vlo;

    float* patch = patches + wid * 16 * 20;
    const int pr = lane >> 1;
    const int pc = (lane & 1) * 8;
#pragma unroll
    for (int i = 0; i < 4; i++)
#pragma unroll
        for (int j = 0; j < 4; j++) {
            wmma::store_matrix_sync(patch, acc[i][j], 20, wmma::mem_row_major);
            __syncwarp();
            const int row = m0 + wm * 64 + i * 16 + pr;
            const int col = n0w + wn * 64 + j * 16 + pc;
            float vv[8];
#pragma unroll
            for (int e = 0; e < 8; e++)
                vv[e] = patch[pr * 20 + pc + e] + biasv[col + e];
            uint32_t hh[4], ll[4];
#pragma unroll
            for (int e = 0; e < 4; e++)
                split_pack(vv[2 * e], vv[2 * e + 1], hh[e], ll[e]);
            *(uint4*)&Ch[(size_t)row * Cc + col] = make_uint4(hh[0], hh[1], hh[2], hh[3]);
            *(uint4*)&Cl[(size_t)row * Cc + col] = make_uint4(ll[0], ll[1], ll[2], ll[3]);
            __syncwarp();
        }
}

// ---------------------------------------------------------------------------
// Final projection GEMM — proven R7 kernel (2-stage register prefetch).
// ---------------------------------------------------------------------------
#define WBM 128
#define WBN 128
static constexpr int GT = 128 * ASTR;
static constexpr int G_TILES_BYTES = 2 * 4 * GT * 2;          // 49152
static constexpr int G_PATCH_BYTES = 8 * 16 * 20 * 4;         // 10240
static constexpr int G_SMEM = G_TILES_BYTES + G_PATCH_BYTES;  // 59392

__global__ __launch_bounds__(256)
void gemm_wmma_out(const __nv_bfloat16* __restrict__ Ahi,
                   const __nv_bfloat16* __restrict__ Alo,
                   const __nv_bfloat16* __restrict__ Bhi,
                   const __nv_bfloat16* __restrict__ Blo,
                   const float* __restrict__ bias,
                   float* __restrict__ Cout,
                   int M, int N, int K)
{
    extern __shared__ char gsm[];
    __nv_bfloat16* tiles = (__nv_bfloat16*)gsm;
    float* patches = (float*)(gsm + G_TILES_BYTES);

    const int tid = threadIdx.x;
    const int wid = tid >> 5;
    const int lane = tid & 31;
    const int wm = wid & 3;
    const int wn = wid >> 2;
    const int m0 = blockIdx.y * WBM;
    const int n0 = blockIdx.x * WBN;

    const int lr = tid >> 1;
    const int lc = (tid & 1) * 8;
    const __nv_bfloat16* srcs[4] = {
        Ahi + (size_t)(m0 + lr) * K + lc,
        Alo + (size_t)(m0 + lr) * K + lc,
        Bhi + (size_t)(n0 + lr) * K + lc,
        Blo + (size_t)(n0 + lr) * K + lc };

    uint4 rg[4];
#pragma unroll
    for (int op = 0; op < 4; op++) rg[op] = *(const uint4*)(srcs[op]);
#pragma unroll
    for (int op = 0; op < 4; op++)
        *(uint4*)(tiles + op * GT + lr * ASTR + lc) = rg[op];
    __syncthreads();

    wmma::fragment<wmma::accumulator, 16, 16, 16, float> acc[2][4];
#pragma unroll
    for (int i = 0; i < 2; i++)
#pragma unroll
        for (int j = 0; j < 4; j++)
            wmma::fill_fragment(acc[i][j], 0.0f);

    int cur = 0;
    for (int k0 = 0; k0 < K; k0 += 16) {
        const bool more = (k0 + 16 < K);
        if (more) {
#pragma unroll
            for (int op = 0; op < 4; op++)
                rg[op] = *(const uint4*)(srcs[op] + k0 + 16);
        }

        __nv_bfloat16* sAh = tiles + (cur * 4 + 0) * GT;
        __nv_bfloat16* sAl = tiles + (cur * 4 + 1) * GT;
        __nv_bfloat16* sBh = tiles + (cur * 4 + 2) * GT;
        __nv_bfloat16* sBl = tiles + (cur * 4 + 3) * GT;

        wmma::fragment<wmma::matrix_a, 16, 16, 16, __nv_bfloat16, wmma::row_major> ah[2], al[2];
#pragma unroll
        for (int i = 0; i < 2; i++) {
            wmma::load_matrix_sync(ah[i], &sAh[(wm * 32 + i * 16) * ASTR], ASTR);
            wmma::load_matrix_sync(al[i], &sAl[(wm * 32 + i * 16) * ASTR], ASTR);
        }
#pragma unroll
        for (int j = 0; j < 4; j++) {
            wmma::fragment<wmma::matrix_b, 16, 16, 16, __nv_bfloat16, wmma::col_major> bh, bl;
            wmma::load_matrix_sync(bh, &sBh[(wn * 64 + j * 16) * ASTR], ASTR);
            wmma::load_matrix_sync(bl, &sBl[(wn * 64 + j * 16) * ASTR], ASTR);
#pragma unroll
            for (int i = 0; i < 2; i++) {
                wmma::mma_sync(acc[i][j], ah[i], bh, acc[i][j]);
                wmma::mma_sync(acc[i][j], al[i], bh, acc[i][j]);
                wmma::mma_sync(acc[i][j], ah[i], bl, acc[i][j]);
            }
        }
        if (more) {
            int nxt = cur ^ 1;
#pragma unroll
            for (int op = 0; op < 4; op++)
                *(uint4*)(tiles + (nxt * 4 + op) * GT + lr * ASTR + lc) = rg[op];
        }
        __syncthreads();
        cur ^= 1;
    }

    float* patch = patches + wid * 16 * 20;
    const int pr = lane >> 1;
    const int pc = (lane & 1) * 8;
#pragma unroll
    for (int i = 0; i < 2; i++)
#pragma unroll
        for (int j = 0; j < 4; j++) {
            wmma::store_matrix_sync(patch, acc[i][j], 20, wmma::mem_row_major);
            __syncwarp();
            const int row = m0 + wm * 32 + i * 16 + pr;
            const int col = n0 + wn * 64 + j * 16 + pc;
            float vv[8];
#pragma unroll
            for (int e = 0; e < 8; e++)
                vv[e] = patch[pr * 20 + pc + e] + bias[col + e];
            *(float4*)&Cout[(size_t)row * N + col] =
                make_float4(vv[0], vv[1], vv[2], vv[3]);
            *(float4*)&Cout[(size_t)row * N + col + 4] =
                make_float4(vv[4], vv[5], vv[6], vv[7]);
            __syncwarp();
        }
}

// ---------------------------------------------------------------------------
// Flash attention — double-buffered cp.async K/V staging (R11, re-bench).
// Q (hi/lo) static; K/V hi/lo per-stage buffers; wait_group<1> overlap.
// smem = 110592 B -> still 2 CTAs/SM.
// ---------------------------------------------------------------------------
static constexpr int AST = 72;
static constexpr int O_QH = 0;
static constexpr int O_QL = O_QH + 128 * AST;            // 9216
static constexpr int KV_BASE = O_QL + 128 * AST;         // 18432
static constexpr int KVB = 4 * 64 * AST;                 // 18432 elems per buffer
static constexpr int KO_KH = 0;
static constexpr int KO_KL = 64 * AST;
static constexpr int KO_VH = 2 * 64 * AST;
static constexpr int KO_VL = 3 * 64 * AST;
static constexpr int ATT_SMEM = (KV_BASE + 2 * KVB) * 2;  // 110592 bytes

__global__ __launch_bounds__(256)
void attn_mma(const __nv_bfloat16* __restrict__ Qhi, const __nv_bfloat16* __restrict__ Qlo,
              const __nv_bfloat16* __restrict__ Khi, const __nv_bfloat16* __restrict__ Klo,
              const __nv_bfloat16* __restrict__ Vhi, const __nv_bfloat16* __restrict__ Vlo,
              __nv_bfloat16* __restrict__ Yhi, __nv_bfloat16* __restrict__ Ylo)
{
    extern __shared__ char smraw[];
    __nv_bfloat16* sb = (__nv_bfloat16*)smraw;
    const uint32_t sb_u = smem_u32(sb);

    const int qi = blockIdx.x, h = blockIdx.y, b = blockIdx.z;
    const int tid = threadIdx.x, wid = tid >> 5, lane = tid & 31;
    const int qb = qi * 128;
    const int wrow0 = wid * 16;
    const size_t gbase = (size_t)b * Tc * Cc + (size_t)h * Dc;
    const int nst = 2 * qi + 2;

    const int arr = tid >> 6;
    const int ci = tid & 63;
    const __nv_bfloat16* garr =
        (arr == 0) ? Khi : (arr == 1) ? Klo : (arr == 2) ? Vhi : Vlo;
    const uint32_t arr_off =
        (arr == 0) ? KO_KH : (arr == 1) ? KO_KL : (arr == 2) ? KO_VH : KO_VL;
    const __nv_bfloat16* gsrc_row = garr + gbase + (size_t)ci * Cc;

    auto prefetch_kv = [&](int st) {
        const uint32_t dst = sb_u +
            (uint32_t)((KV_BASE + (st & 1) * KVB + arr_off + ci * AST) * 2);
        const __nv_bfloat16* s = gsrc_row + (size_t)(st * 64) * Cc;
#pragma unroll
        for (int ch = 0; ch < 8; ch++)
            cp16(dst + ch * 16, s + ch * 8);
    };

    prefetch_kv(0); cp_commit();
    if (nst > 1) prefetch_kv(1);
    cp_commit();   // uniform group accounting (possibly empty)

    // stage Q (hi/lo) with plain loads, once
#pragma unroll
    for (int u = 0; u < 4; u++) {
        int id = tid + u * 256;
        int r = id >> 3, ch = id & 7;
        const size_t goff = gbase + (size_t)(qb + r) * Cc + ch * 8;
        *(uint4*)&sb[O_QH + r * AST + ch * 8] = *(const uint4*)(Qhi + goff);
        *(uint4*)&sb[O_QL + r * AST + ch * 8] = *(const uint4*)(Qlo + goff);
    }

    const uint32_t qh_u = sb_u + O_QH * 2, ql_u = sb_u + O_QL * 2;
    const int i7 = lane & 7, g = lane >> 3;
    const uint32_t aQoff = ((wrow0 + i7 + (g & 1) * 8) * AST + (g >> 1) * 8) * 2;
    const int l15 = lane & 15;
    const int bi = l15 & 7, bh8 = (l15 >> 3) * 8;

    float m_A = -1e30f, m_B = -1e30f, l_A = 0.f, l_B = 0.f;
    float oacc[8][4];
#pragma unroll
    for (int n = 0; n < 8; n++)
#pragma unroll
        for (int e = 0; e < 4; e++) oacc[n][e] = 0.f;

    for (int st = 0; st < nst; st++) {
        cp_wait<1>();
        __syncthreads();

        const uint32_t kvb = sb_u + (uint32_t)((KV_BASE + (st & 1) * KVB) * 2);
        const uint32_t kh_u = kvb + KO_KH * 2, kl_u = kvb + KO_KL * 2;
        const uint32_t vh_u = kvb + KO_VH * 2, vl_u = kvb + KO_VL * 2;

        float sacc[8][4];
#pragma unroll
        for (int n = 0; n < 8; n++)
#pragma unroll
            for (int e = 0; e < 4; e++) sacc[n][e] = 0.f;

#pragma unroll
        for (int kk = 0; kk < 4; kk++) {
            uint32_t a0, a1, a2, a3, c0, c1, c2, c3;
            ldsm4(a0, a1, a2, a3, qh_u + aQoff + kk * 32);
            ldsm4(c0, c1, c2, c3, ql_u + aQoff + kk * 32);
#pragma unroll
            for (int n = 0; n < 8; n++) {
                const uint32_t boff = ((n * 8 + bi) * AST + bh8 + kk * 16) * 2;
                uint32_t bh0, bh1, bl0, bl1;
                ldsm2(bh0, bh1, kh_u + boff);
                ldsm2(bl0, bl1, kl_u + boff);
                mma16816(sacc[n], a0, a1, a2, a3, bh0, bh1);
                mma16816(sacc[n], c0, c1, c2, c3, bh0, bh1);
                mma16816(sacc[n], a0, a1, a2, a3, bl0, bl1);
            }
        }

#pragma unroll
        for (int n = 0; n < 8; n++)
#pragma unroll
            for (int e = 0; e < 4; e++) sacc[n][e] *= 0.125f;

        if (st >= 2 * qi) {
            const int rowAg = qb + wrow0 + (lane >> 2);
            const int rowBg = rowAg + 8;
#pragma unroll
            for (int n = 0; n < 8; n++) {
                const int cg = st * 64 + n * 8 + (lane & 3) * 2;
                if (cg     > rowAg) sacc[n][0] = -1e30f;
                if (cg + 1 > rowAg) sacc[n][1] = -1e30f;
                if (cg     > rowBg) sacc[n][2] = -1e30f;
                if (cg + 1 > rowBg) sacc[n][3] = -1e30f;
            }
        }

        float mA = -1e30f, mB = -1e30f;
#pragma unroll
        for (int n = 0; n < 8; n++) {
            mA = fmaxf(mA, fmaxf(sacc[n][0], sacc[n][1]));
            mB = fmaxf(mB, fmaxf(sacc[n][2], sacc[n][3]));
        }
        mA = fmaxf(mA, __shfl_xor_sync(0xffffffffu, mA, 1));
        mA = fmaxf(mA, __shfl_xor_sync(0xffffffffu, mA, 2));
        mB = fmaxf(mB, __shfl_xor_sync(0xffffffffu, mB, 1));
        mB = fmaxf(mB, __shfl_xor_sync(0xffffffffu, mB, 2));
        const float mnA = fmaxf(m_A, mA), mnB = fmaxf(m_B, mB);
        const float alA = __expf(m_A - mnA), alB = __expf(m_B - mnB);
        m_A = mnA; m_B = mnB;

        float lsA = 0.f, lsB = 0.f;
#pragma unroll
        for (int n = 0; n < 8; n++) {
            sacc[n][0] = __expf(sacc[n][0] - mnA);
            sacc[n][1] = __expf(sacc[n][1] - mnA);
            sacc[n][2] = __expf(sacc[n][2] - mnB);
            sacc[n][3] = __expf(sacc[n][3] - mnB);
            lsA += sacc[n][0] + sacc[n][1];
            lsB += sacc[n][2] + sacc[n][3];
        }
        lsA += __shfl_xor_sync(0xffffffffu, lsA, 1);
        lsA += __shfl_xor_sync(0xffffffffu, lsA, 2);
        lsB += __shfl_xor_sync(0xffffffffu, lsB, 1);
        lsB += __shfl_xor_sync(0xffffffffu, lsB, 2);
        l_A = l_A * alA + lsA;
        l_B = l_B * alB + lsB;
#pragma unroll
        for (int n = 0; n < 8; n++) {
            oacc[n][0] *= alA; oacc[n][1] *= alA;
            oacc[n][2] *= alB; oacc[n][3] *= alB;
        }

#pragma unroll
        for (int ks = 0; ks < 4; ks++) {
            uint32_t ah0, ah1, ah2, ah3, al0, al1, al2, al3;
            split_pack(sacc[2 * ks][0],     sacc[2 * ks][1],     ah0, al0);
            split_pack(sacc[2 * ks][2],     sacc[2 * ks][3],     ah1, al1);
            split_pack(sacc[2 * ks + 1][0], sacc[2 * ks + 1][1], ah2, al2);
            split_pack(sacc[2 * ks + 1][2], sacc[2 * ks + 1][3], ah3, al3);
            const uint32_t vrow = (16 * ks + l15) * AST;
#pragma unroll
            for (int n = 0; n < 8; n++) {
                uint32_t bh0, bh1, bl0, bl1;
                ldsm2t(bh0, bh1, vh_u + (vrow + n * 8) * 2);
                ldsm2t(bl0, bl1, vl_u + (vrow + n * 8) * 2);
                mma16816(oacc[n], ah0, ah1, ah2, ah3, bh0, bh1);
                mma16816(oacc[n], al0, al1, al2, al3, bh0, bh1);
                mma16816(oacc[n], ah0, ah1, ah2, ah3, bl0, bl1);
            }
        }

        __syncthreads();
        if (st + 2 < nst) prefetch_kv(st + 2);
        cp_commit();
    }

    const float invA = 1.f / l_A, invB = 1.f / l_B;
    const int rowA = qb + wrow0 + (lane >> 2);
    const size_t ybA = ((size_t)b * Tc + rowA) * Cc + h * Dc + (lane & 3) * 2;
    const size_t ybB = ybA + (size_t)8 * Cc;
#pragma unroll
    for (int n = 0; n < 8; n++) {
        uint32_t hh, ll;
        split_pack(oacc[n][0] * invA, oacc[n][1] * invA, hh, ll);
        *(uint32_t*)&Yhi[ybA + n * 8] = hh;
        *(uint32_t*)&Ylo[ybA + n * 8] = ll;
        split_pack(oacc[n][2] * invB, oacc[n][3] * invB, hh, ll);
        *(uint32_t*)&Yhi[ybB + n * 8] = hh;
        *(uint32_t*)&Ylo[ybB + n * 8] = ll;
    }
}

// ---------------------------------------------------------------------------
extern "C" void kernel_launch(void* const* d_in, const int* in_sizes, int n_in,
                              void* d_out, int out_size)
{
    (void)in_sizes; (void)n_in; (void)out_size;
    const float* x  = (const float*)d_in[0];
    const float* Wq = (const float*)d_in[1];
    const float* bq = (const float*)d_in[2];
    const float* Wk = (const float*)d_in[3];
    const float* bk = (const float*)d_in[4];
    const float* Wv = (const float*)d_in[5];
    const float* bv = (const float*)d_in[6];
    const float* Wp = (const float*)d_in[7];
    const float* bp = (const float*)d_in[8];
    float* out = (float*)d_out;

    __nv_bfloat16 *xhi, *xlo, *qhi, *qlo, *khi, *klo, *vhi, *vlo, *yhi, *ylo, *whi, *wlo;
    cudaGetSymbolAddress((void**)&xhi, g_xhi);
    cudaGetSymbolAddress((void**)&xlo, g_xlo);
    cudaGetSymbolAddress((void**)&qhi, g_qhi);
    cudaGetSymbolAddress((void**)&qlo, g_qlo);
    cudaGetSymbolAddress((void**)&khi, g_khi);
    cudaGetSymbolAddress((void**)&klo, g_klo);
    cudaGetSymbolAddress((void**)&vhi, g_vhi);
    cudaGetSymbolAddress((void**)&vlo, g_vlo);
    cudaGetSymbolAddress((void**)&yhi, g_yhi);
    cudaGetSymbolAddress((void**)&ylo, g_ylo);
    cudaGetSymbolAddress((void**)&whi, g_whi);
    cudaGetSymbolAddress((void**)&wlo, g_wlo);

    cudaFuncSetAttribute(gemm_qkv_fused,
                         cudaFuncAttributeMaxDynamicSharedMemorySize, Q_SMEM);
    cudaFuncSetAttribute(gemm_wmma_out,
                         cudaFuncAttributeMaxDynamicSharedMemorySize, G_SMEM);
    cudaFuncSetAttribute(attn_mma,
                         cudaFuncAttributeMaxDynamicSharedMemorySize, ATT_SMEM);

    // hi/lo splits of inputs
    split_bf16<<<(ELEMS / 4 + 255) / 256, 256>>>(x, xhi, xlo, ELEMS / 4);
    const float* Ws[4] = {Wq, Wk, Wv, Wp};
    for (int i = 0; i < 4; i++)
        split_bf16<<<(WELEMS / 4 + 255) / 256, 256>>>(
            Ws[i], whi + (size_t)i * WELEMS, wlo + (size_t)i * WELEMS, WELEMS / 4);

    // Fused QKV projections
    dim3 gq(24, Mrows / QBM);   // (24, 32)
    gemm_qkv_fused<<<gq, 256, Q_SMEM>>>(xhi, xlo, whi, wlo, bq, bk, bv,
                                        qhi, qlo, khi, klo, vhi, vlo);

    // attention (hi/lo in, hi/lo out), double-buffered cp.async staging
    dim3 ga(Tc / 128, Hc, Bc);  // (16, 16, 4)
    attn_mma<<<ga, 256, ATT_SMEM>>>(qhi, qlo, khi, klo, vhi, vlo, yhi, ylo);

    // output projection -> fp32
    dim3 gg(Cc / WBN, Mrows / WBM);   // (8, 64)
    gemm_wmma_out<<<gg, 256, G_SMEM>>>(yhi, ylo, whi + 3 * (size_t)WELEMS,
        wlo + 3 * (size_t)WELEMS, bp, out, Mrows, Cc, Cc);
}

// round 16
// speedup vs baseline: 1.6779x; 1.6779x over previous
#include <cuda_runtime.h>
#include <cuda_bf16.h>
#include <mma.h>
#include <cstdint>

using namespace nvcuda;

// Problem constants
static constexpr int Bc = 4, Tc = 2048, Cc = 1024, Hc = 16, Dc = 64;
static constexpr int Mrows = Bc * Tc;            // 8192
static constexpr int ELEMS = Mrows * Cc;         // 8388608
static constexpr int WELEMS = Cc * Cc;           // 1048576

// Scratch (device globals — no allocation allowed). All hi/lo bf16 pairs.
__device__ __nv_bfloat16 g_xhi[ELEMS], g_xlo[ELEMS];
__device__ __nv_bfloat16 g_qhi[ELEMS], g_qlo[ELEMS];
__device__ __nv_bfloat16 g_khi[ELEMS], g_klo[ELEMS];
__device__ __nv_bfloat16 g_vhi[ELEMS], g_vlo[ELEMS];
__device__ __nv_bfloat16 g_yhi[ELEMS], g_ylo[ELEMS];
__device__ __nv_bfloat16 g_whi[4][WELEMS], g_wlo[4][WELEMS];

// ---------------------------------------------------------------------------
// PTX primitives (plain-sm_103 legal)
// ---------------------------------------------------------------------------
__device__ __forceinline__ uint32_t smem_u32(const void* p) {
    uint32_t a;
    asm("{ .reg .u64 t; cvta.to.shared.u64 t, %1; cvt.u32.u64 %0, t; }" : "=r"(a) : "l"(p));
    return a;
}
__device__ __forceinline__ void cp16(uint32_t dst, const void* src) {
    asm volatile("cp.async.cg.shared.global [%0], [%1], 16;" :: "r"(dst), "l"(src));
}
__device__ __forceinline__ void cp_commit() { asm volatile("cp.async.commit_group;" ::: "memory"); }
template<int N> __device__ __forceinline__ void cp_wait() {
    asm volatile("cp.async.wait_group %0;" :: "n"(N) : "memory");
}
__device__ __forceinline__ void ldsm4(uint32_t& r0, uint32_t& r1, uint32_t& r2, uint32_t& r3, uint32_t a) {
    asm volatile("ldmatrix.sync.aligned.m8n8.x4.shared.b16 {%0,%1,%2,%3}, [%4];"
                 : "=r"(r0), "=r"(r1), "=r"(r2), "=r"(r3) : "r"(a));
}
__device__ __forceinline__ void ldsm2(uint32_t& r0, uint32_t& r1, uint32_t a) {
    asm volatile("ldmatrix.sync.aligned.m8n8.x2.shared.b16 {%0,%1}, [%2];"
                 : "=r"(r0), "=r"(r1) : "r"(a));
}
__device__ __forceinline__ void ldsm2t(uint32_t& r0, uint32_t& r1, uint32_t a) {
    asm volatile("ldmatrix.sync.aligned.m8n8.x2.trans.shared.b16 {%0,%1}, [%2];"
                 : "=r"(r0), "=r"(r1) : "r"(a));
}
__device__ __forceinline__ void mma16816(float* c, uint32_t a0, uint32_t a1, uint32_t a2, uint32_t a3,
                                         uint32_t b0, uint32_t b1) {
    asm volatile("mma.sync.aligned.m16n8k16.row.col.f32.bf16.bf16.f32 "
                 "{%0,%1,%2,%3}, {%4,%5,%6,%7}, {%8,%9}, {%0,%1,%2,%3};"
                 : "+f"(c[0]), "+f"(c[1]), "+f"(c[2]), "+f"(c[3])
                 : "r"(a0), "r"(a1), "r"(a2), "r"(a3), "r"(b0), "r"(b1));
}
__device__ __forceinline__ void split_pack(float x, float y, uint32_t& hi, uint32_t& lo) {
    __nv_bfloat16 hx = __float2bfloat16_rn(x), hy = __float2bfloat16_rn(y);
    float lx = x - __bfloat162float(hx), ly = y - __bfloat162float(hy);
    __nv_bfloat162 hv(hx, hy);
    __nv_bfloat162 lv(__float2bfloat16_rn(lx), __float2bfloat16_rn(ly));
    hi = *reinterpret_cast<uint32_t*>(&hv);
    lo = *reinterpret_cast<uint32_t*>(&lv);
}

// ---------------------------------------------------------------------------
// fp32 -> bf16 hi/lo split conversion. x version + fused 4-weight version.
// ---------------------------------------------------------------------------
__global__ __launch_bounds__(256)
void split_bf16(const float* __restrict__ in,
                __nv_bfloat16* __restrict__ hi,
                __nv_bfloat16* __restrict__ lo, int n4)
{
    int i = blockIdx.x * blockDim.x + threadIdx.x;
    if (i >= n4) return;
    int idx = i * 4;
    float4 v = *(const float4*)(in + idx);
    uint32_t h0, l0, h1, l1;
    split_pack(v.x, v.y, h0, l0);
    split_pack(v.z, v.w, h1, l1);
    *(uint2*)(hi + idx) = make_uint2(h0, h1);
    *(uint2*)(lo + idx) = make_uint2(l0, l1);
}

// one launch for all 4 weight matrices: blockIdx.y selects the matrix
__global__ __launch_bounds__(256)
void split_bf16_w4(const float* __restrict__ w0, const float* __restrict__ w1,
                   const float* __restrict__ w2, const float* __restrict__ w3,
                   __nv_bfloat16* __restrict__ hi,   // [4][WELEMS]
                   __nv_bfloat16* __restrict__ lo)
{
    const int m = blockIdx.y;
    const float* in = (m == 0) ? w0 : (m == 1) ? w1 : (m == 2) ? w2 : w3;
    int i = blockIdx.x * blockDim.x + threadIdx.x;
    if (i >= WELEMS / 4) return;
    int idx = i * 4;
    float4 v = *(const float4*)(in + idx);
    uint32_t h0, l0, h1, l1;
    split_pack(v.x, v.y, h0, l0);
    split_pack(v.z, v.w, h1, l1);
    *(uint2*)(hi + (size_t)m * WELEMS + idx) = make_uint2(h0, h1);
    *(uint2*)(lo + (size_t)m * WELEMS + idx) = make_uint2(l0, l1);
}

// ---------------------------------------------------------------------------
// Fused QKV GEMM (proven 1186us config): block 256x128, warp 64x64,
// 3-stage cp.async. blockIdx.x in [0,24): which = x/8 selects Wq/Wk/Wv.
// ---------------------------------------------------------------------------
#define ASTR 24
static constexpr int QBM = 256;
static constexpr int Q_SAH = 0;
static constexpr int Q_SAL = 256 * ASTR;
static constexpr int Q_SBH = 2 * 256 * ASTR;
static constexpr int Q_SBL = Q_SBH + 128 * ASTR;
static constexpr int Q_STAGE_E = Q_SBL + 128 * ASTR;
static constexpr int Q_STAGES = 3;
static constexpr int Q_TILES_BYTES = Q_STAGES * Q_STAGE_E * 2;   // 110592
static constexpr int Q_PATCH_BYTES = 8 * 16 * 20 * 4;            // 10240
static constexpr int Q_SMEM = Q_TILES_BYTES + Q_PATCH_BYTES;     // 120832

__global__ __launch_bounds__(256)
void gemm_qkv_fused(const __nv_bfloat16* __restrict__ Xhi,
                    const __nv_bfloat16* __restrict__ Xlo,
                    const __nv_bfloat16* __restrict__ Whi,
                    const __nv_bfloat16* __restrict__ Wlo,
                    const float* __restrict__ bq,
                    const float* __restrict__ bk,
                    const float* __restrict__ bv,
                    __nv_bfloat16* __restrict__ Qhi, __nv_bfloat16* __restrict__ Qlo,
                    __nv_bfloat16* __restrict__ Khi, __nv_bfloat16* __restrict__ Klo,
                    __nv_bfloat16* __restrict__ Vhi, __nv_bfloat16* __restrict__ Vlo)
{
    extern __shared__ char gsm[];
    __nv_bfloat16* tiles = (__nv_bfloat16*)gsm;
    float* patches = (float*)(gsm + Q_TILES_BYTES);
    const uint32_t tiles_u = smem_u32(tiles);

    const int tid = threadIdx.x;
    const int wid = tid >> 5;
    const int lane = tid & 31;
    const int wm = wid & 3;
    const int wn = wid >> 2;
    const int m0 = blockIdx.y * QBM;
    const int gn0 = blockIdx.x * 128;
    const int which = gn0 >> 10;
    const int n0w = gn0 & 1023;
    const int K = Cc;

    const __nv_bfloat16* Bh = Whi + (size_t)which * WELEMS;
    const __nv_bfloat16* Bl = Wlo + (size_t)which * WELEMS;

    auto prefetch = [&](int stage, int k0) {
        const uint32_t sb = tiles_u + (uint32_t)(stage * Q_STAGE_E * 2);
#pragma unroll
        for (int u = 0; u < 4; u++) {
            int idx = tid + u * 256;
            int op = idx >> 9;
            int rem = idx & 511;
            int r = rem >> 1, ch = rem & 1;
            const __nv_bfloat16* s =
                (op ? Xlo : Xhi) + (size_t)(m0 + r) * K + k0 + ch * 8;
            cp16(sb + (uint32_t)(((op ? Q_SAL : Q_SAH) + r * ASTR) * 2 + ch * 16), s);
        }
#pragma unroll
        for (int u = 0; u < 2; u++) {
            int idx = tid + u * 256;
            int op = idx >> 8;
            int rem = idx & 255;
            int r = rem >> 1, ch = rem & 1;
            const __nv_bfloat16* s =
                (op ? Bl : Bh) + (size_t)(n0w + r) * K + k0 + ch * 8;
            cp16(sb + (uint32_t)(((op ? Q_SBL : Q_SBH) + r * ASTR) * 2 + ch * 16), s);
        }
    };

    prefetch(0, 0);  cp_commit();
    prefetch(1, 16); cp_commit();

    wmma::fragment<wmma::accumulator, 16, 16, 16, float> acc[4][4];
#pragma unroll
    for (int i = 0; i < 4; i++)
#pragma unroll
        for (int j = 0; j < 4; j++)
            wmma::fill_fragment(acc[i][j], 0.0f);

    const int KT = K / 16;
    for (int kt = 0; kt < KT; kt++) {
        const int s = kt % Q_STAGES;
        if (kt == KT - 1) cp_wait<0>(); else cp_wait<1>();
        __syncthreads();

        __nv_bfloat16* st = tiles + s * Q_STAGE_E;
        wmma::fragment<wmma::matrix_a, 16, 16, 16, __nv_bfloat16, wmma::row_major> ah[4], al[4];
#pragma unroll
        for (int i = 0; i < 4; i++) {
            wmma::load_matrix_sync(ah[i], st + Q_SAH + (wm * 64 + i * 16) * ASTR, ASTR);
            wmma::load_matrix_sync(al[i], st + Q_SAL + (wm * 64 + i * 16) * ASTR, ASTR);
        }
#pragma unroll
        for (int j = 0; j < 4; j++) {
            wmma::fragment<wmma::matrix_b, 16, 16, 16, __nv_bfloat16, wmma::col_major> bh, bl;
            wmma::load_matrix_sync(bh, st + Q_SBH + (wn * 64 + j * 16) * ASTR, ASTR);
            wmma::load_matrix_sync(bl, st + Q_SBL + (wn * 64 + j * 16) * ASTR, ASTR);
#pragma unroll
            for (int i = 0; i < 4; i++) {
                wmma::mma_sync(acc[i][j], ah[i], bh, acc[i][j]);
                wmma::mma_sync(acc[i][j], al[i], bh, acc[i][j]);
                wmma::mma_sync(acc[i][j], ah[i], bl, acc[i][j]);
            }
        }
        if (kt + 2 < KT) { prefetch((kt + 2) % Q_STAGES, (kt + 2) * 16); cp_commit(); }
    }

    const float* biasv = (which == 0) ? bq : (which == 1) ? bk : bv;
    __nv_bfloat16* Ch = (which == 0) ? Qhi : (which == 1) ? Khi : Vhi;
    __nv_bfloat16* Cl = (which == 0) ? Qlo : (which == 1) ? Klo : Vlo;

    float* patch = patches + wid * 16 * 20;
    const int pr = lane >> 1;
    const int pc = (lane & 1) * 8;
#pragma unroll
    for (int i = 0; i < 4; i++)
#pragma unroll
        for (int j = 0; j < 4; j++) {
            wmma::store_matrix_sync(patch, acc[i][j], 20, wmma::mem_row_major);
            __syncwarp();
            const int row = m0 + wm * 64 + i * 16 + pr;
            const int col = n0w + wn * 64 + j * 16 + pc;
            float vv[8];
#pragma unroll
            for (int e = 0; e < 8; e++)
                vv[e] = patch[pr * 20 + pc + e] + biasv[col + e];
            uint32_t hh[4], ll[4];
#pragma unroll
            for (int e = 0; e < 4; e++)
                split_pack(vv[2 * e], vv[2 * e + 1], hh[e], ll[e]);
            *(uint4*)&Ch[(size_t)row * Cc + col] = make_uint4(hh[0], hh[1], hh[2], hh[3]);
            *(uint4*)&Cl[(size_t)row * Cc + col] = make_uint4(ll[0], ll[1], ll[2], ll[3]);
            __syncwarp();
        }
}

// ---------------------------------------------------------------------------
// Final projection GEMM — proven R7 kernel (2-stage register prefetch).
// ---------------------------------------------------------------------------
#define WBM 128
#define WBN 128
static constexpr int GT = 128 * ASTR;
static constexpr int G_TILES_BYTES = 2 * 4 * GT * 2;          // 49152
static constexpr int G_PATCH_BYTES = 8 * 16 * 20 * 4;         // 10240
static constexpr int G_SMEM = G_TILES_BYTES + G_PATCH_BYTES;  // 59392

__global__ __launch_bounds__(256)
void gemm_wmma_out(const __nv_bfloat16* __restrict__ Ahi,
                   const __nv_bfloat16* __restrict__ Alo,
                   const __nv_bfloat16* __restrict__ Bhi,
                   const __nv_bfloat16* __restrict__ Blo,
                   const float* __restrict__ bias,
                   float* __restrict__ Cout,
                   int M, int N, int K)
{
    extern __shared__ char gsm[];
    __nv_bfloat16* tiles = (__nv_bfloat16*)gsm;
    float* patches = (float*)(gsm + G_TILES_BYTES);

    const int tid = threadIdx.x;
    const int wid = tid >> 5;
    const int lane = tid & 31;
    const int wm = wid & 3;
    const int wn = wid >> 2;
    const int m0 = blockIdx.y * WBM;
    const int n0 = blockIdx.x * WBN;

    const int lr = tid >> 1;
    const int lc = (tid & 1) * 8;
    const __nv_bfloat16* srcs[4] = {
        Ahi + (size_t)(m0 + lr) * K + lc,
        Alo + (size_t)(m0 + lr) * K + lc,
        Bhi + (size_t)(n0 + lr) * K + lc,
        Blo + (size_t)(n0 + lr) * K + lc };

    uint4 rg[4];
#pragma unroll
    for (int op = 0; op < 4; op++) rg[op] = *(const uint4*)(srcs[op]);
#pragma unroll
    for (int op = 0; op < 4; op++)
        *(uint4*)(tiles + op * GT + lr * ASTR + lc) = rg[op];
    __syncthreads();

    wmma::fragment<wmma::accumulator, 16, 16, 16, float> acc[2][4];
#pragma unroll
    for (int i = 0; i < 2; i++)
#pragma unroll
        for (int j = 0; j < 4; j++)
            wmma::fill_fragment(acc[i][j], 0.0f);

    int cur = 0;
    for (int k0 = 0; k0 < K; k0 += 16) {
        const bool more = (k0 + 16 < K);
        if (more) {
#pragma unroll
            for (int op = 0; op < 4; op++)
                rg[op] = *(const uint4*)(srcs[op] + k0 + 16);
        }

        __nv_bfloat16* sAh = tiles + (cur * 4 + 0) * GT;
        __nv_bfloat16* sAl = tiles + (cur * 4 + 1) * GT;
        __nv_bfloat16* sBh = tiles + (cur * 4 + 2) * GT;
        __nv_bfloat16* sBl = tiles + (cur * 4 + 3) * GT;

        wmma::fragment<wmma::matrix_a, 16, 16, 16, __nv_bfloat16, wmma::row_major> ah[2], al[2];
#pragma unroll
        for (int i = 0; i < 2; i++) {
            wmma::load_matrix_sync(ah[i], &sAh[(wm * 32 + i * 16) * ASTR], ASTR);
            wmma::load_matrix_sync(al[i], &sAl[(wm * 32 + i * 16) * ASTR], ASTR);
        }
#pragma unroll
        for (int j = 0; j < 4; j++) {
            wmma::fragment<wmma::matrix_b, 16, 16, 16, __nv_bfloat16, wmma::col_major> bh, bl;
            wmma::load_matrix_sync(bh, &sBh[(wn * 64 + j * 16) * ASTR], ASTR);
            wmma::load_matrix_sync(bl, &sBl[(wn * 64 + j * 16) * ASTR], ASTR);
#pragma unroll
            for (int i = 0; i < 2; i++) {
                wmma::mma_sync(acc[i][j], ah[i], bh, acc[i][j]);
                wmma::mma_sync(acc[i][j], al[i], bh, acc[i][j]);
                wmma::mma_sync(acc[i][j], ah[i], bl, acc[i][j]);
            }
        }
        if (more) {
            int nxt = cur ^ 1;
#pragma unroll
            for (int op = 0; op < 4; op++)
                *(uint4*)(tiles + (nxt * 4 + op) * GT + lr * ASTR + lc) = rg[op];
        }
        __syncthreads();
        cur ^= 1;
    }

    float* patch = patches + wid * 16 * 20;
    const int pr = lane >> 1;
    const int pc = (lane & 1) * 8;
#pragma unroll
    for (int i = 0; i < 2; i++)
#pragma unroll
        for (int j = 0; j < 4; j++) {
            wmma::store_matrix_sync(patch, acc[i][j], 20, wmma::mem_row_major);
            __syncwarp();
            const int row = m0 + wm * 32 + i * 16 + pr;
            const int col = n0 + wn * 64 + j * 16 + pc;
            float vv[8];
#pragma unroll
            for (int e = 0; e < 8; e++)
                vv[e] = patch[pr * 20 + pc + e] + bias[col + e];
            *(float4*)&Cout[(size_t)row * N + col] =
                make_float4(vv[0], vv[1], vv[2], vv[3]);
            *(float4*)&Cout[(size_t)row * N + col + 4] =
                make_float4(vv[4], vv[5], vv[6], vv[7]);
            __syncwarp();
        }
}

// ---------------------------------------------------------------------------
// Flash attention — plain LDG->STS staging (measured-best 1186us config).
// ---------------------------------------------------------------------------
static constexpr int AST = 72;
static constexpr int O_QH = 0;
static constexpr int O_QL = O_QH + 128 * AST;
static constexpr int O_KH = O_QL + 128 * AST;
static constexpr int O_KL = O_KH + 64 * AST;
static constexpr int O_VH = O_KL + 64 * AST;
static constexpr int O_VL = O_VH + 64 * AST;
static constexpr int ATT_SMEM = (O_VL + 64 * AST) * 2;   // 73728 bytes

__global__ __launch_bounds__(256)
void attn_mma(const __nv_bfloat16* __restrict__ Qhi, const __nv_bfloat16* __restrict__ Qlo,
              const __nv_bfloat16* __restrict__ Khi, const __nv_bfloat16* __restrict__ Klo,
              const __nv_bfloat16* __restrict__ Vhi, const __nv_bfloat16* __restrict__ Vlo,
              __nv_bfloat16* __restrict__ Yhi, __nv_bfloat16* __restrict__ Ylo)
{
    extern __shared__ char smraw[];
    __nv_bfloat16* sb = (__nv_bfloat16*)smraw;
    const uint32_t sb_u = smem_u32(sb);

    const int qi = blockIdx.x, h = blockIdx.y, b = blockIdx.z;
    const int tid = threadIdx.x, wid = tid >> 5, lane = tid & 31;
    const int qb = qi * 128;
    const int wrow0 = wid * 16;
    const size_t gbase = (size_t)b * Tc * Cc + (size_t)h * Dc;

#pragma unroll
    for (int u = 0; u < 4; u++) {
        int id = tid + u * 256;
        int r = id >> 3, ch = id & 7;
        const size_t goff = gbase + (size_t)(qb + r) * Cc + ch * 8;
        *(uint4*)&sb[O_QH + r * AST + ch * 8] = *(const uint4*)(Qhi + goff);
        *(uint4*)&sb[O_QL + r * AST + ch * 8] = *(const uint4*)(Qlo + goff);
    }

    const uint32_t qh_u = sb_u + O_QH * 2, ql_u = sb_u + O_QL * 2;
    const uint32_t kh_u = sb_u + O_KH * 2, kl_u = sb_u + O_KL * 2;
    const uint32_t vh_u = sb_u + O_VH * 2, vl_u = sb_u + O_VL * 2;
    const int i7 = lane & 7, g = lane >> 3;
    const uint32_t aQoff = ((wrow0 + i7 + (g & 1) * 8) * AST + (g >> 1) * 8) * 2;
    const int l15 = lane & 15;
    const int bi = l15 & 7, bh8 = (l15 >> 3) * 8;

    float m_A = -1e30f, m_B = -1e30f, l_A = 0.f, l_B = 0.f;
    float oacc[8][4];
#pragma unroll
    for (int n = 0; n < 8; n++)
#pragma unroll
        for (int e = 0; e < 4; e++) oacc[n][e] = 0.f;

    const int nst = 2 * qi + 2;
    for (int st = 0; st < nst; st++) {
        __syncthreads();
#pragma unroll
        for (int u = 0; u < 8; u++) {
            int id = tid + u * 256;
            int arr = id >> 9;
            int rem = id & 511;
            int r = rem >> 3, ch = rem & 7;
            const __nv_bfloat16* garr =
                (arr == 0) ? Khi : (arr == 1) ? Klo : (arr == 2) ? Vhi : Vlo;
            const uint32_t arr_off =
                (arr == 0) ? O_KH : (arr == 1) ? O_KL : (arr == 2) ? O_VH : O_VL;
            *(uint4*)&sb[arr_off + r * AST + ch * 8] =
                *(const uint4*)(garr + gbase + (size_t)(st * 64 + r) * Cc + ch * 8);
        }
        __syncthreads();

        float sacc[8][4];
#pragma unroll
        for (int n = 0; n < 8; n++)
#pragma unroll
            for (int e = 0; e < 4; e++) sacc[n][e] = 0.f;

#pragma unroll
        for (int kk = 0; kk < 4; kk++) {
            uint32_t a0, a1, a2, a3, c0, c1, c2, c3;
            ldsm4(a0, a1, a2, a3, qh_u + aQoff + kk * 32);
            ldsm4(c0, c1, c2, c3, ql_u + aQoff + kk * 32);
#pragma unroll
            for (int n = 0; n < 8; n++) {
                const uint32_t boff = ((n * 8 + bi) * AST + bh8 + kk * 16) * 2;
                uint32_t bh0, bh1, bl0, bl1;
                ldsm2(bh0, bh1, kh_u + boff);
                ldsm2(bl0, bl1, kl_u + boff);
                mma16816(sacc[n], a0, a1, a2, a3, bh0, bh1);
                mma16816(sacc[n], c0, c1, c2, c3, bh0, bh1);
                mma16816(sacc[n], a0, a1, a2, a3, bl0, bl1);
            }
        }

#pragma unroll
        for (int n = 0; n < 8; n++)
#pragma unroll
            for (int e = 0; e < 4; e++) sacc[n][e] *= 0.125f;

        if (st >= 2 * qi) {
            const int rowAg = qb + wrow0 + (lane >> 2);
            const int rowBg = rowAg + 8;
#pragma unroll
            for (int n = 0; n < 8; n++) {
                const int cg = st * 64 + n * 8 + (lane & 3) * 2;
                if (cg     > rowAg) sacc[n][0] = -1e30f;
                if (cg + 1 > rowAg) sacc[n][1] = -1e30f;
                if (cg     > rowBg) sacc[n][2] = -1e30f;
                if (cg + 1 > rowBg) sacc[n][3] = -1e30f;
            }
        }

        float mA = -1e30f, mB = -1e30f;
#pragma unroll
        for (int n = 0; n < 8; n++) {
            mA = fmaxf(mA, fmaxf(sacc[n][0], sacc[n][1]));
            mB = fmaxf(mB, fmaxf(sacc[n][2], sacc[n][3]));
        }
        mA = fmaxf(mA, __shfl_xor_sync(0xffffffffu, mA, 1));
        mA = fmaxf(mA, __shfl_xor_sync(0xffffffffu, mA, 2));
        mB = fmaxf(mB, __shfl_xor_sync(0xffffffffu, mB, 1));
        mB = fmaxf(mB, __shfl_xor_sync(0xffffffffu, mB, 2));
        const float mnA = fmaxf(m_A, mA), mnB = fmaxf(m_B, mB);
        const float alA = __expf(m_A - mnA), alB = __expf(m_B - mnB);
        m_A = mnA; m_B = mnB;

        float lsA = 0.f, lsB = 0.f;
#pragma unroll
        for (int n = 0; n < 8; n++) {
            sacc[n][0] = __expf(sacc[n][0] - mnA);
            sacc[n][1] = __expf(sacc[n][1] - mnA);
            sacc[n][2] = __expf(sacc[n][2] - mnB);
            sacc[n][3] = __expf(sacc[n][3] - mnB);
            lsA += sacc[n][0] + sacc[n][1];
            lsB += sacc[n][2] + sacc[n][3];
        }
        lsA += __shfl_xor_sync(0xffffffffu, lsA, 1);
        lsA += __shfl_xor_sync(0xffffffffu, lsA, 2);
        lsB += __shfl_xor_sync(0xffffffffu, lsB, 1);
        lsB += __shfl_xor_sync(0xffffffffu, lsB, 2);
        l_A = l_A * alA + lsA;
        l_B = l_B * alB + lsB;
#pragma unroll
        for (int n = 0; n < 8; n++) {
            oacc[n][0] *= alA; oacc[n][1] *= alA;
            oacc[n][2] *= alB; oacc[n][3] *= alB;
        }

#pragma unroll
        for (int ks = 0; ks < 4; ks++) {
            uint32_t ah0, ah1, ah2, ah3, al0, al1, al2, al3;
            split_pack(sacc[2 * ks][0],     sacc[2 * ks][1],     ah0, al0);
            split_pack(sacc[2 * ks][2],     sacc[2 * ks][3],     ah1, al1);
            split_pack(sacc[2 * ks + 1][0], sacc[2 * ks + 1][1], ah2, al2);
            split_pack(sacc[2 * ks + 1][2], sacc[2 * ks + 1][3], ah3, al3);
            const uint32_t vrow = (16 * ks + l15) * AST;
#pragma unroll
            for (int n = 0; n < 8; n++) {
                uint32_t bh0, bh1, bl0, bl1;
                ldsm2t(bh0, bh1, vh_u + (vrow + n * 8) * 2);
                ldsm2t(bl0, bl1, vl_u + (vrow + n * 8) * 2);
                mma16816(oacc[n], ah0, ah1, ah2, ah3, bh0, bh1);
                mma16816(oacc[n], al0, al1, al2, al3, bh0, bh1);
                mma16816(oacc[n], ah0, ah1, ah2, ah3, bl0, bl1);
            }
        }
    }

    const float invA = 1.f / l_A, invB = 1.f / l_B;
    const int rowA = qb + wrow0 + (lane >> 2);
    const size_t ybA = ((size_t)b * Tc + rowA) * Cc + h * Dc + (lane & 3) * 2;
    const size_t ybB = ybA + (size_t)8 * Cc;
#pragma unroll
    for (int n = 0; n < 8; n++) {
        uint32_t hh, ll;
        split_pack(oacc[n][0] * invA, oacc[n][1] * invA, hh, ll);
        *(uint32_t*)&Yhi[ybA + n * 8] = hh;
        *(uint32_t*)&Ylo[ybA + n * 8] = ll;
        split_pack(oacc[n][2] * invB, oacc[n][3] * invB, hh, ll);
        *(uint32_t*)&Yhi[ybB + n * 8] = hh;
        *(uint32_t*)&Ylo[ybB + n * 8] = ll;
    }
}

// ---------------------------------------------------------------------------
extern "C" void kernel_launch(void* const* d_in, const int* in_sizes, int n_in,
                              void* d_out, int out_size)
{
    (void)in_sizes; (void)n_in; (void)out_size;
    const float* x  = (const float*)d_in[0];
    const float* Wq = (const float*)d_in[1];
    const float* bq = (const float*)d_in[2];
    const float* Wk = (const float*)d_in[3];
    const float* bk = (const float*)d_in[4];
    const float* Wv = (const float*)d_in[5];
    const float* bv = (const float*)d_in[6];
    const float* Wp = (const float*)d_in[7];
    const float* bp = (const float*)d_in[8];
    float* out = (float*)d_out;

    __nv_bfloat16 *xhi, *xlo, *qhi, *qlo, *khi, *klo, *vhi, *vlo, *yhi, *ylo, *whi, *wlo;
    cudaGetSymbolAddress((void**)&xhi, g_xhi);
    cudaGetSymbolAddress((void**)&xlo, g_xlo);
    cudaGetSymbolAddress((void**)&qhi, g_qhi);
    cudaGetSymbolAddress((void**)&qlo, g_qlo);
    cudaGetSymbolAddress((void**)&khi, g_khi);
    cudaGetSymbolAddress((void**)&klo, g_klo);
    cudaGetSymbolAddress((void**)&vhi, g_vhi);
    cudaGetSymbolAddress((void**)&vlo, g_vlo);
    cudaGetSymbolAddress((void**)&yhi, g_yhi);
    cudaGetSymbolAddress((void**)&ylo, g_ylo);
    cudaGetSymbolAddress((void**)&whi, g_whi);
    cudaGetSymbolAddress((void**)&wlo, g_wlo);

    cudaFuncSetAttribute(gemm_qkv_fused,
                         cudaFuncAttributeMaxDynamicSharedMemorySize, Q_SMEM);
    cudaFuncSetAttribute(gemm_wmma_out,
                         cudaFuncAttributeMaxDynamicSharedMemorySize, G_SMEM);
    cudaFuncSetAttribute(attn_mma,
                         cudaFuncAttributeMaxDynamicSharedMemorySize, ATT_SMEM);

    // hi/lo splits of inputs: x (1 launch) + all 4 weights (1 launch)
    split_bf16<<<(ELEMS / 4 + 255) / 256, 256>>>(x, xhi, xlo, ELEMS / 4);
    dim3 gw((WELEMS / 4 + 255) / 256, 4);
    split_bf16_w4<<<gw, 256>>>(Wq, Wk, Wv, Wp, whi, wlo);

    // Fused QKV projections
    dim3 gq(24, Mrows / QBM);   // (24, 32)
    gemm_qkv_fused<<<gq, 256, Q_SMEM>>>(xhi, xlo, whi, wlo, bq, bk, bv,
                                        qhi, qlo, khi, klo, vhi, vlo);

    // attention (hi/lo in, hi/lo out)
    dim3 ga(Tc / 128, Hc, Bc);  // (16, 16, 4)
    attn_mma<<<ga, 256, ATT_SMEM>>>(qhi, qlo, khi, klo, vhi, vlo, yhi, ylo);

    // output projection -> fp32
    dim3 gg(Cc / WBN, Mrows / WBM);   // (8, 64)
    gemm_wmma_out<<<gg, 256, G_SMEM>>>(yhi, ylo, whi + 3 * (size_t)WELEMS,
        wlo + 3 * (size_t)WELEMS, bp, out, Mrows, Cc, Cc);
}